// round 14
// baseline (speedup 1.0000x reference)
#include <cuda_runtime.h>

#define NUM_USERS 50000
#define NUM_ITEMS 50000
#define D 64
#define DV 16
#define N_NODES (NUM_USERS + NUM_ITEMS)
#define N_EDGES 500000
#define NNZ_G 1000000
#define NNZ_GX 2000000
#define N_GXE (NNZ_GX * 2)                  // split halves: 4M entries
#define BATCH 8192

#define BINS_PER_BLOCK 2048                 // 256 threads x 8 bins
#define XN_BLOCKS 49                        // ceil(100000/2048) gx node bins
#define G_BLOCKS  49                        // ceil(100000/2048) g row bins

// ---- static device scratch (zero-init at load; replay-safe state machine) ----
__device__ float g_A[(size_t)N_NODES * D];
__device__ float g_B[(size_t)N_NODES * D];     // zeroed by k_combine each layer
__device__ float g_U[(size_t)N_NODES * D];     // ditto
__device__ float g_acc[(size_t)N_NODES * D];   // zeroed by k_initcount each call
__device__ float g_deg[N_NODES];               // counted in k_initcount, zeroed by k_dot
__device__ int2  g_pe[N_EDGES];                // {tu[e]|ti[e]<<16, i2c[ti[e]]}

// gx half-entries sorted by DESTINATION NODE: 100k bins, avg segment 40
__device__ int  g_xcnt[N_NODES];               // counted, then zeroed by k_scanA
__device__ int  g_xcur[N_NODES];
__device__ int  g_xpart[XN_BLOCKS];
__device__ int4 g_es4[N_GXE];                  // {src_node, dst_node, vbits, catoff}

// g nnz sorted by DESTINATION row: 100k bins, avg segment 10
__device__ int  g_gcnt[N_NODES];
__device__ int  g_gcur[N_NODES];
__device__ int  g_gpart[G_BLOCKS];
__device__ int4 g_gs4[NNZ_G];                  // {col, row, vbits, 0}

// fire-and-forget vector reduction (RED.E.ADD.F32x4), sm_90+
__device__ __forceinline__ void red_add_f32x4(float4* addr, float4 v) {
    asm volatile("red.global.add.v4.f32 [%0], {%1, %2, %3, %4};"
                 :: "l"(addr), "f"(v.x), "f"(v.y), "f"(v.z), "f"(v.w)
                 : "memory");
}
__device__ __forceinline__ void f4add(float4& a, const float4& b) {
    a.x += b.x; a.y += b.y; a.z += b.z; a.w += b.w;
}
__device__ __forceinline__ void f4fma(float4& a, float v, const float4& x) {
    a.x += v * x.x; a.y += v * x.y; a.z += v * x.z; a.w += v * x.w;
}

// 1: init A/acc + edge-pack table + degree + both bin counts
__global__ void k_initcount(const float* __restrict__ ue, const float* __restrict__ ie,
                            const int* __restrict__ gxr, const int* __restrict__ grows,
                            const int* __restrict__ tu, const int* __restrict__ ti,
                            const int* __restrict__ i2c) {
    int t = blockIdx.x * blockDim.x + threadIdx.x;
    if (t < N_NODES * DV) {
        float4 v;
        if (t < NUM_USERS * DV) v = ((const float4*)ue)[t];
        else                    v = ((const float4*)ie)[t - NUM_USERS * DV];
        ((float4*)g_A)[t]   = v;
        ((float4*)g_acc)[t] = make_float4(0.f, 0.f, 0.f, 0.f);
    }
    if (t < NNZ_GX) {
        int r = gxr[t];
        atomicAdd(&g_xcnt[tu[r]], 1);
        atomicAdd(&g_xcnt[NUM_USERS + ti[r]], 1);
    }
    if (t < NNZ_G) atomicAdd(&g_gcnt[grows[t]], 1);
    if (t < N_EDGES) {
        int u = tu[t], it = ti[t];
        atomicAdd(&g_deg[u], 1.f);
        atomicAdd(&g_deg[NUM_USERS + it], 1.f);
        g_pe[t] = make_int2((int)((unsigned)u | ((unsigned)it << 16)), i2c[it]);
    }
}

// 2: block-local scans over node bins; zero counts behind
__global__ void k_scanA() {
    __shared__ int sh[256];
    int b = blockIdx.x;
    int tid = threadIdx.x;
    int *cnt, *cur, *part;
    int base_bin, pidx;
    const int n = N_NODES;
    if (b < XN_BLOCKS) { cnt = g_xcnt; cur = g_xcur; part = g_xpart; base_bin = b * BINS_PER_BLOCK; pidx = b; }
    else               { cnt = g_gcnt; cur = g_gcur; part = g_gpart; base_bin = (b - XN_BLOCKS) * BINS_PER_BLOCK; pidx = b - XN_BLOCKS; }
    int i0 = base_bin + tid * 8;
    int c[8], pre[8];
    #pragma unroll
    for (int k = 0; k < 8; ++k) {
        int i = i0 + k;
        c[k] = (i < n) ? cnt[i] : 0;
    }
    pre[0] = 0;
    #pragma unroll
    for (int k = 1; k < 8; ++k) pre[k] = pre[k - 1] + c[k - 1];
    int s = pre[7] + c[7];
    sh[tid] = s;
    __syncthreads();
    for (int o = 1; o < 256; o <<= 1) {
        int v = (tid >= o) ? sh[tid - o] : 0;
        __syncthreads();
        sh[tid] += v;
        __syncthreads();
    }
    int base = (tid == 0) ? 0 : sh[tid - 1];
    #pragma unroll
    for (int k = 0; k < 8; ++k) {
        int i = i0 + k;
        if (i < n) { cur[i] = base + pre[k]; cnt[i] = 0; }
    }
    if (tid == 255) part[pidx] = sh[255];
}

// 3: scan the block-sum arrays
__global__ void k_scanB() {
    __shared__ int sh[256];
    int tid = threadIdx.x;
    int v = (tid < XN_BLOCKS) ? g_xpart[tid] : 0;
    sh[tid] = v;
    __syncthreads();
    for (int o = 1; o < 256; o <<= 1) {
        int u = (tid >= o) ? sh[tid - o] : 0;
        __syncthreads();
        sh[tid] += u;
        __syncthreads();
    }
    if (tid < XN_BLOCKS) g_xpart[tid] = sh[tid] - v;
    __syncthreads();
    int w = (tid < G_BLOCKS) ? g_gpart[tid] : 0;
    sh[tid] = w;
    __syncthreads();
    for (int o = 1; o < 256; o <<= 1) {
        int u = (tid >= o) ? sh[tid - o] : 0;
        __syncthreads();
        sh[tid] += u;
        __syncthreads();
    }
    if (tid < G_BLOCKS) g_gpart[tid] = sh[tid] - w;
}

// 4: scatter: split each gx nnz into user-half + item-half node-sorted entries
__global__ void k_scatter(const int* __restrict__ gxr, const int* __restrict__ gxc,
                          const float* __restrict__ gxv,
                          const int* __restrict__ grows, const int* __restrict__ gcols,
                          const float* __restrict__ gvals) {
    int t = blockIdx.x * blockDim.x + threadIdx.x;
    if (t < NNZ_GX) {
        int r = gxr[t];
        int c = gxc[t];
        int2 pc = g_pe[c];
        int2 pr = g_pe[r];
        int vb = __float_as_int(gxv[t]);
        unsigned sc = (unsigned)pc.x, dr = (unsigned)pr.x;
        int su = (int)(sc & 0xFFFFu);
        int si = NUM_USERS + (int)(sc >> 16);
        int du = (int)(dr & 0xFFFFu);
        int di = NUM_USERS + (int)(dr >> 16);
        int catbase = pc.y * 32;
        int pu = atomicAdd(&g_xcur[du], 1) + g_xpart[du >> 11];
        g_es4[pu] = make_int4(su, du, vb, catbase);
        int pi = atomicAdd(&g_xcur[di], 1) + g_xpart[di >> 11];
        g_es4[pi] = make_int4(si, di, vb, catbase + 16);
    }
    if (t < NNZ_G) {
        int row = grows[t];
        int p = atomicAdd(&g_gcur[row], 1) + g_gpart[row >> 11];
        g_gs4[p] = make_int4(gcols[t], row, __float_as_int(gvals[t]), 0);
    }
}

// 5: push spmm, 8 nnz/thread, run-merge REDs by row (avg segment 10)
__global__ void __launch_bounds__(256) k_spmm_g() {
    int t = blockIdx.x * blockDim.x + threadIdx.x;   // < NNZ_G/8 * 16 = 2M
    int p = t >> 4;
    int j = t & 15;
    if (p >= NNZ_G / 8) return;
    int4 E[8];
    #pragma unroll
    for (int k = 0; k < 8; ++k) E[k] = g_gs4[8 * p + k];
    const float4* Av = (const float4*)g_A;
    float4 x[8];
    #pragma unroll
    for (int k = 0; k < 8; ++k) x[k] = Av[E[k].x * DV + j];
    float4* Bv = (float4*)g_B;
    float4 acc = make_float4(0.f, 0.f, 0.f, 0.f);
    f4fma(acc, __int_as_float(E[0].z), x[0]);
    int cur = E[0].y;
    #pragma unroll
    for (int k = 1; k < 8; ++k) {
        if (E[k].y != cur) {
            red_add_f32x4(Bv + cur * DV + j, acc);
            cur = E[k].y;
            acc = make_float4(0.f, 0.f, 0.f, 0.f);
        }
        f4fma(acc, __int_as_float(E[k].z), x[k]);
    }
    red_add_f32x4(Bv + cur * DV + j, acc);
}

// 6: gx push over node-sorted half-entries, 8/thread, run-merge (avg segment 40)
template <int LAYER0>
__global__ void __launch_bounds__(256) k_gx(const float* __restrict__ cat) {
    int t = blockIdx.x * blockDim.x + threadIdx.x;   // < N_GXE/8 * 16 = 8M
    int p = t >> 4;
    int j = t & 15;
    if (p >= N_GXE / 8) return;
    int4 E[8];
    #pragma unroll
    for (int k = 0; k < 8; ++k) E[k] = g_es4[8 * p + k];
    const float4* Bv = (const float4*)g_B;
    const float* catf = cat;
    float4 x[8];
    #pragma unroll
    for (int k = 0; k < 8; ++k) {
        x[k] = Bv[E[k].x * DV + j];
        if (LAYER0) {
            float4 c = *(const float4*)(catf + 4 * (E[k].w + j));
            f4add(x[k], c);
        }
    }
    float4* Uv = (float4*)g_U;
    float4 acc = make_float4(0.f, 0.f, 0.f, 0.f);
    f4fma(acc, __int_as_float(E[0].z), x[0]);
    int cur = E[0].y;
    #pragma unroll
    for (int k = 1; k < 8; ++k) {
        if (E[k].y != cur) {
            red_add_f32x4(Uv + cur * DV + j, acc);
            cur = E[k].y;
            acc = make_float4(0.f, 0.f, 0.f, 0.f);
        }
        f4fma(acc, __int_as_float(E[k].z), x[k]);
    }
    red_add_f32x4(Uv + cur * DV + j, acc);
}

// A = 0.5 * (U/(deg+1e-9) + B);  acc += A;  zero B,U for next layer/replay
__global__ void k_combine() {
    int t0 = (blockIdx.x * blockDim.x + threadIdx.x) * 2;
    if (t0 >= N_NODES * DV) return;
    float4 z = make_float4(0.f, 0.f, 0.f, 0.f);
    #pragma unroll
    for (int q = 0; q < 2; ++q) {
        int t = t0 + q;
        int n = t >> 4;
        float inv = 0.5f / (g_deg[n] + 1e-9f);
        float4 u = ((const float4*)g_U)[t];
        float4 b = ((const float4*)g_B)[t];
        float4 a;
        a.x = u.x * inv + 0.5f * b.x;
        a.y = u.y * inv + 0.5f * b.y;
        a.z = u.z * inv + 0.5f * b.z;
        a.w = u.w * inv + 0.5f * b.w;
        ((float4*)g_A)[t] = a;
        float4 ac = ((float4*)g_acc)[t];
        f4add(ac, a);
        ((float4*)g_acc)[t] = ac;
        ((float4*)g_B)[t] = z;
        ((float4*)g_U)[t] = z;
    }
}

// gamma[b] = dot(acc[u], acc[50000+i]) / 9; zero deg for next replay
__global__ void k_dot(const int* __restrict__ users, const int* __restrict__ items,
                      float* __restrict__ out) {
    int t = blockIdx.x * blockDim.x + threadIdx.x;
    if (t < N_NODES) g_deg[t] = 0.f;
    int b = t >> 5;
    if (b >= BATCH) return;
    int lane = t & 31;
    const float2* au = (const float2*)(g_acc + (size_t)users[b] * D);
    const float2* ai = (const float2*)(g_acc + (size_t)(NUM_USERS + items[b]) * D);
    float2 x = au[lane], y = ai[lane];
    float s = x.x * y.x + x.y * y.y;
    #pragma unroll
    for (int o = 16; o; o >>= 1) s += __shfl_down_sync(0xffffffffu, s, o);
    if (lane == 0) out[b] = s * (1.f / 9.f);
}

extern "C" void kernel_launch(void* const* d_in, const int* in_sizes, int n_in,
                              void* d_out, int out_size) {
    const float* user_emb = (const float*)d_in[0];
    const float* item_emb = (const float*)d_in[1];
    const float* cat_emb  = (const float*)d_in[2];
    const float* g_vals   = (const float*)d_in[3];
    const float* gx_vals  = (const float*)d_in[4];
    const int*   g_rows   = (const int*)d_in[5];
    const int*   g_cols   = (const int*)d_in[6];
    const int*   gx_rows  = (const int*)d_in[7];
    const int*   gx_cols  = (const int*)d_in[8];
    const int*   tu       = (const int*)d_in[9];
    const int*   ti       = (const int*)d_in[10];
    const int*   i2c      = (const int*)d_in[11];
    const int*   users    = (const int*)d_in[12];
    const int*   items    = (const int*)d_in[13];
    float* out = (float*)d_out;

    const int TB = 256;
    int big_grid  = (NNZ_GX + TB - 1) / TB;              // 7813
    int comb_grid = (N_NODES * DV / 2 + TB - 1) / TB;    // 3125
    int g_grid    = (NNZ_G / 8 * 16 + TB - 1) / TB;      // 7813
    int gx_grid   = (N_GXE / 8 * 16) / TB;               // 31250
    int dot_grid  = (BATCH * 32 + TB - 1) / TB;          // 1024

    k_initcount<<<big_grid, TB>>>(user_emb, item_emb, gx_rows, g_rows, tu, ti, i2c); // 1
    k_scanA<<<XN_BLOCKS + G_BLOCKS, TB>>>();                                         // 2
    k_scanB<<<1, TB>>>();                                                            // 3
    k_scatter<<<big_grid, TB>>>(gx_rows, gx_cols, gx_vals, g_rows, g_cols, g_vals);  // 4 <- profiled
    for (int L = 0; L < 3; ++L) {
        k_spmm_g<<<g_grid, TB>>>();
        if (L == 0) k_gx<1><<<gx_grid, TB>>>(cat_emb);
        else        k_gx<0><<<gx_grid, TB>>>(cat_emb);
        k_combine<<<comb_grid, TB>>>();
    }
    k_dot<<<dot_grid, TB>>>(users, items, out);
}

// round 15
// speedup vs baseline: 1.0546x; 1.0546x over previous
#include <cuda_runtime.h>

#define NUM_USERS 50000
#define NUM_ITEMS 50000
#define D 64
#define DV 16
#define N_NODES (NUM_USERS + NUM_ITEMS)
#define N_EDGES 500000
#define NNZ_G 1000000
#define NNZ_GX 2000000
#define BATCH 8192

#define BINS_PER_BLOCK 2048                 // 256 threads x 8 bins
#define GX_BLOCKS 245                       // ceil(500000/2048) gx dst-edge bins
#define G_BLOCKS  49                        // ceil(100000/2048) g row bins
#define PREP_T 500000                       // threads in batched prep kernels

// ---- static device scratch (zero-init at load; replay-safe state machine) ----
__device__ float g_A[(size_t)N_NODES * D];
__device__ float g_B[(size_t)N_NODES * D];     // zeroed by k_combine each layer
__device__ float g_U[(size_t)N_NODES * D];     // ditto
__device__ float g_acc[(size_t)N_NODES * D];   // zeroed by k_initcount each call
__device__ float g_deg[N_NODES];               // counted in k_initcount, zeroed by k_dot
__device__ int2  g_pe[N_EDGES];                // {tu[e]|ti[e]<<16, i2c[ti[e]]}

// gx nnz sorted by DESTINATION edge (gxr): 500k bins, avg segment 4
__device__ int  g_ecnt[N_EDGES];               // counted, then zeroed by k_scanA
__device__ int  g_ecur[N_EDGES];
__device__ int  g_part[GX_BLOCKS];
__device__ int4 g_es4[NNZ_GX];                 // {srcpack, dstpack, vbits, cidx}

// g nnz sorted by DESTINATION row: 100k bins, avg segment 10
__device__ int  g_gcnt[N_NODES];
__device__ int  g_gcur[N_NODES];
__device__ int  g_gpart[G_BLOCKS];
__device__ int4 g_gs4[NNZ_G];                  // {col, row, vbits, 0}

// fire-and-forget vector reduction (RED.E.ADD.F32x4), sm_90+
__device__ __forceinline__ void red_add_f32x4(float4* addr, float4 v) {
    asm volatile("red.global.add.v4.f32 [%0], {%1, %2, %3, %4};"
                 :: "l"(addr), "f"(v.x), "f"(v.y), "f"(v.z), "f"(v.w)
                 : "memory");
}
__device__ __forceinline__ void f4add(float4& a, const float4& b) {
    a.x += b.x; a.y += b.y; a.z += b.z; a.w += b.w;
}

// 1: batched init + counts: 4 strided A/acc chunks, 4 gx counts, 2 g counts,
//    1 deg/pe per thread — 10+ independent chains for MLP
__global__ void k_initcount(const float* __restrict__ ue, const float* __restrict__ ie,
                            const int* __restrict__ gxr, const int* __restrict__ grows,
                            const int* __restrict__ tu, const int* __restrict__ ti,
                            const int* __restrict__ i2c) {
    int t = blockIdx.x * blockDim.x + threadIdx.x;
    if (t >= PREP_T) return;
    #pragma unroll
    for (int k = 0; k < 4; ++k) {
        int i = t + k * PREP_T;
        if (i < N_NODES * DV) {
            float4 v;
            if (i < NUM_USERS * DV) v = ((const float4*)ue)[i];
            else                    v = ((const float4*)ie)[i - NUM_USERS * DV];
            ((float4*)g_A)[i]   = v;
            ((float4*)g_acc)[i] = make_float4(0.f, 0.f, 0.f, 0.f);
        }
    }
    int4 r4 = ((const int4*)gxr)[t];
    atomicAdd(&g_ecnt[r4.x], 1);
    atomicAdd(&g_ecnt[r4.y], 1);
    atomicAdd(&g_ecnt[r4.z], 1);
    atomicAdd(&g_ecnt[r4.w], 1);
    int2 gr2 = ((const int2*)grows)[t];
    atomicAdd(&g_gcnt[gr2.x], 1);
    atomicAdd(&g_gcnt[gr2.y], 1);
    int u = tu[t], it = ti[t];
    atomicAdd(&g_deg[u], 1.f);
    atomicAdd(&g_deg[NUM_USERS + it], 1.f);
    g_pe[t] = make_int2((int)((unsigned)u | ((unsigned)it << 16)), i2c[it]);
}

// 2: block-local scans; zero counts behind
__global__ void k_scanA() {
    __shared__ int sh[256];
    int b = blockIdx.x;
    int tid = threadIdx.x;
    int *cnt, *cur, *part;
    int n, base_bin, pidx;
    if (b < GX_BLOCKS) { cnt = g_ecnt; cur = g_ecur; part = g_part;  n = N_EDGES; base_bin = b * BINS_PER_BLOCK; pidx = b; }
    else               { cnt = g_gcnt; cur = g_gcur; part = g_gpart; n = N_NODES; base_bin = (b - GX_BLOCKS) * BINS_PER_BLOCK; pidx = b - GX_BLOCKS; }
    int i0 = base_bin + tid * 8;
    int c[8], pre[8];
    #pragma unroll
    for (int k = 0; k < 8; ++k) {
        int i = i0 + k;
        c[k] = (i < n) ? cnt[i] : 0;
    }
    pre[0] = 0;
    #pragma unroll
    for (int k = 1; k < 8; ++k) pre[k] = pre[k - 1] + c[k - 1];
    int s = pre[7] + c[7];
    sh[tid] = s;
    __syncthreads();
    for (int o = 1; o < 256; o <<= 1) {
        int v = (tid >= o) ? sh[tid - o] : 0;
        __syncthreads();
        sh[tid] += v;
        __syncthreads();
    }
    int base = (tid == 0) ? 0 : sh[tid - 1];
    #pragma unroll
    for (int k = 0; k < 8; ++k) {
        int i = i0 + k;
        if (i < n) { cur[i] = base + pre[k]; cnt[i] = 0; }
    }
    if (tid == 255) part[pidx] = sh[255];
}

// 3: scan the block-sum arrays
__global__ void k_scanB() {
    __shared__ int sh[256];
    int tid = threadIdx.x;
    int v = (tid < GX_BLOCKS) ? g_part[tid] : 0;
    sh[tid] = v;
    __syncthreads();
    for (int o = 1; o < 256; o <<= 1) {
        int u = (tid >= o) ? sh[tid - o] : 0;
        __syncthreads();
        sh[tid] += u;
        __syncthreads();
    }
    if (tid < GX_BLOCKS) g_part[tid] = sh[tid] - v;
    __syncthreads();
    int w = (tid < G_BLOCKS) ? g_gpart[tid] : 0;
    sh[tid] = w;
    __syncthreads();
    for (int o = 1; o < 256; o <<= 1) {
        int u = (tid >= o) ? sh[tid - o] : 0;
        __syncthreads();
        sh[tid] += u;
        __syncthreads();
    }
    if (tid < G_BLOCKS) g_gpart[tid] = sh[tid] - w;
}

// 4: batched scatter: 4 gx nnz + 2 g nnz per thread (6 independent chains)
__global__ void k_scatter(const int* __restrict__ gxr, const int* __restrict__ gxc,
                          const float* __restrict__ gxv,
                          const int* __restrict__ grows, const int* __restrict__ gcols,
                          const float* __restrict__ gvals) {
    int t = blockIdx.x * blockDim.x + threadIdx.x;
    if (t >= PREP_T) return;
    int4   r4 = ((const int4*)gxr)[t];
    int4   c4 = ((const int4*)gxc)[t];
    float4 v4 = ((const float4*)gxv)[t];
    int r[4] = {r4.x, r4.y, r4.z, r4.w};
    int c[4] = {c4.x, c4.y, c4.z, c4.w};
    float vv[4] = {v4.x, v4.y, v4.z, v4.w};
    int2 pc[4], pr[4];
    #pragma unroll
    for (int k = 0; k < 4; ++k) { pc[k] = g_pe[c[k]]; pr[k] = g_pe[r[k]]; }
    #pragma unroll
    for (int k = 0; k < 4; ++k) {
        int p = atomicAdd(&g_ecur[r[k]], 1) + g_part[r[k] >> 11];
        g_es4[p] = make_int4(pc[k].x, pr[k].x, __float_as_int(vv[k]), pc[k].y);
    }
    int2   row2 = ((const int2*)grows)[t];
    int2   col2 = ((const int2*)gcols)[t];
    float2 gv2  = ((const float2*)gvals)[t];
    int p0 = atomicAdd(&g_gcur[row2.x], 1) + g_gpart[row2.x >> 11];
    g_gs4[p0] = make_int4(col2.x, row2.x, __float_as_int(gv2.x), 0);
    int p1 = atomicAdd(&g_gcur[row2.y], 1) + g_gpart[row2.y >> 11];
    g_gs4[p1] = make_int4(col2.y, row2.y, __float_as_int(gv2.y), 0);
}

// 5: push spmm, 4 nnz/thread, run-merge REDs by row (R13-proven)
__global__ void __launch_bounds__(256) k_spmm_g() {
    int t = blockIdx.x * blockDim.x + threadIdx.x;   // < NNZ_G/4 * 16 = 4M
    int p = t >> 4;
    int j = t & 15;
    if (p >= NNZ_G / 4) return;
    int4 E[4];
    #pragma unroll
    for (int k = 0; k < 4; ++k) E[k] = g_gs4[4 * p + k];
    const float4* Av = (const float4*)g_A;
    float4 y[4];
    #pragma unroll
    for (int k = 0; k < 4; ++k) {
        float4 x = Av[E[k].x * DV + j];
        float v = __int_as_float(E[k].z);
        y[k] = make_float4(v * x.x, v * x.y, v * x.z, v * x.w);
    }
    float4* Bv = (float4*)g_B;
    float4 acc = y[0];
    int cur = E[0].y;
    #pragma unroll
    for (int k = 1; k < 4; ++k) {
        if (E[k].y == cur) { f4add(acc, y[k]); }
        else {
            red_add_f32x4(Bv + cur * DV + j, acc);
            cur = E[k].y;
            acc = y[k];
        }
    }
    red_add_f32x4(Bv + cur * DV + j, acc);
}

// 6: gx push, 4 nnz/thread, run-merge RED pairs by dst-pack (R13-proven)
template <int LAYER0>
__global__ void __launch_bounds__(256) k_gx(const float* __restrict__ cat) {
    int t = blockIdx.x * blockDim.x + threadIdx.x;   // < NNZ_GX/4 * 16 = 8M
    int p = t >> 4;
    int j = t & 15;
    if (p >= NNZ_GX / 4) return;
    int4 E[4];
    #pragma unroll
    for (int k = 0; k < 4; ++k) E[k] = g_es4[4 * p + k];
    const float4* Bv = (const float4*)g_B;
    const float4* catv = (const float4*)cat;
    float4 yu[4], yi[4];
    #pragma unroll
    for (int k = 0; k < 4; ++k) {
        unsigned s = (unsigned)E[k].x;
        float4 x0 = Bv[(int)(s & 0xFFFFu) * DV + j];
        float4 x1 = Bv[(NUM_USERS + (int)(s >> 16)) * DV + j];
        if (LAYER0) {
            float4 c0 = catv[E[k].w * 32 + j];
            float4 c1 = catv[E[k].w * 32 + 16 + j];
            f4add(x0, c0);
            f4add(x1, c1);
        }
        float v = __int_as_float(E[k].z);
        yu[k] = make_float4(v * x0.x, v * x0.y, v * x0.z, v * x0.w);
        yi[k] = make_float4(v * x1.x, v * x1.y, v * x1.z, v * x1.w);
    }
    float4* Uv = (float4*)g_U;
    float4 au = yu[0], ai = yi[0];
    unsigned cur = (unsigned)E[0].y;
    #pragma unroll
    for (int k = 1; k < 4; ++k) {
        unsigned d = (unsigned)E[k].y;
        if (d == cur) { f4add(au, yu[k]); f4add(ai, yi[k]); }
        else {
            red_add_f32x4(Uv + (int)(cur & 0xFFFFu) * DV + j, au);
            red_add_f32x4(Uv + (NUM_USERS + (int)(cur >> 16)) * DV + j, ai);
            cur = d;
            au = yu[k];
            ai = yi[k];
        }
    }
    red_add_f32x4(Uv + (int)(cur & 0xFFFFu) * DV + j, au);
    red_add_f32x4(Uv + (NUM_USERS + (int)(cur >> 16)) * DV + j, ai);
}

// A = 0.5 * (U/(deg+1e-9) + B);  acc += A;  zero B,U. LAST layer skips dead A write.
template <int LAST>
__global__ void k_combine() {
    int t0 = (blockIdx.x * blockDim.x + threadIdx.x) * 2;
    if (t0 >= N_NODES * DV) return;
    float4 z = make_float4(0.f, 0.f, 0.f, 0.f);
    #pragma unroll
    for (int q = 0; q < 2; ++q) {
        int t = t0 + q;
        int n = t >> 4;
        float inv = 0.5f / (g_deg[n] + 1e-9f);
        float4 u = ((const float4*)g_U)[t];
        float4 b = ((const float4*)g_B)[t];
        float4 a;
        a.x = u.x * inv + 0.5f * b.x;
        a.y = u.y * inv + 0.5f * b.y;
        a.z = u.z * inv + 0.5f * b.z;
        a.w = u.w * inv + 0.5f * b.w;
        if (!LAST) ((float4*)g_A)[t] = a;
        float4 ac = ((float4*)g_acc)[t];
        f4add(ac, a);
        ((float4*)g_acc)[t] = ac;
        ((float4*)g_B)[t] = z;
        ((float4*)g_U)[t] = z;
    }
}

// gamma[b] = dot(acc[u], acc[50000+i]) / 9; zero deg for next replay
__global__ void k_dot(const int* __restrict__ users, const int* __restrict__ items,
                      float* __restrict__ out) {
    int t = blockIdx.x * blockDim.x + threadIdx.x;
    if (t < N_NODES) g_deg[t] = 0.f;
    int b = t >> 5;
    if (b >= BATCH) return;
    int lane = t & 31;
    const float2* au = (const float2*)(g_acc + (size_t)users[b] * D);
    const float2* ai = (const float2*)(g_acc + (size_t)(NUM_USERS + items[b]) * D);
    float2 x = au[lane], y = ai[lane];
    float s = x.x * y.x + x.y * y.y;
    #pragma unroll
    for (int o = 16; o; o >>= 1) s += __shfl_down_sync(0xffffffffu, s, o);
    if (lane == 0) out[b] = s * (1.f / 9.f);
}

extern "C" void kernel_launch(void* const* d_in, const int* in_sizes, int n_in,
                              void* d_out, int out_size) {
    const float* user_emb = (const float*)d_in[0];
    const float* item_emb = (const float*)d_in[1];
    const float* cat_emb  = (const float*)d_in[2];
    const float* g_vals   = (const float*)d_in[3];
    const float* gx_vals  = (const float*)d_in[4];
    const int*   g_rows   = (const int*)d_in[5];
    const int*   g_cols   = (const int*)d_in[6];
    const int*   gx_rows  = (const int*)d_in[7];
    const int*   gx_cols  = (const int*)d_in[8];
    const int*   tu       = (const int*)d_in[9];
    const int*   ti       = (const int*)d_in[10];
    const int*   i2c      = (const int*)d_in[11];
    const int*   users    = (const int*)d_in[12];
    const int*   items    = (const int*)d_in[13];
    float* out = (float*)d_out;

    const int TB = 256;
    int prep_grid = (PREP_T + TB - 1) / TB;              // 1954
    int comb_grid = (N_NODES * DV / 2 + TB - 1) / TB;    // 3125
    int g_grid    = (NNZ_G / 4 * 16) / TB;               // 15625
    int gx_grid   = (NNZ_GX / 4 * 16) / TB;              // 31250
    int dot_grid  = (BATCH * 32 + TB - 1) / TB;          // 1024

    k_initcount<<<prep_grid, TB>>>(user_emb, item_emb, gx_rows, g_rows, tu, ti, i2c); // 1
    k_scanA<<<GX_BLOCKS + G_BLOCKS, TB>>>();                                          // 2
    k_scanB<<<1, TB>>>();                                                             // 3
    k_scatter<<<prep_grid, TB>>>(gx_rows, gx_cols, gx_vals, g_rows, g_cols, g_vals);  // 4 <- profiled
    for (int L = 0; L < 3; ++L) {
        k_spmm_g<<<g_grid, TB>>>();
        if (L == 0) k_gx<1><<<gx_grid, TB>>>(cat_emb);
        else        k_gx<0><<<gx_grid, TB>>>(cat_emb);
        if (L < 2) k_combine<0><<<comb_grid, TB>>>();
        else       k_combine<1><<<comb_grid, TB>>>();
    }
    k_dot<<<dot_grid, TB>>>(users, items, out);
}

// round 16
// speedup vs baseline: 1.0652x; 1.0101x over previous
#include <cuda_runtime.h>
#include <cuda_fp16.h>

#define NUM_USERS 50000
#define NUM_ITEMS 50000
#define D 64
#define DV 16
#define N_NODES (NUM_USERS + NUM_ITEMS)
#define N_EDGES 500000
#define NNZ_G 1000000
#define NNZ_GX 2000000
#define BATCH 8192

#define BINS_PER_BLOCK 2048                 // 256 threads x 8 bins
#define GX_BLOCKS 245                       // ceil(500000/2048) gx dst-edge bins
#define G_BLOCKS  49                        // ceil(100000/2048) g row bins
#define PREP_T 500000                       // threads in batched prep kernels

// ---- static device scratch (zero-init at load; replay-safe state machine) ----
__device__ __half g_Ah[(size_t)N_NODES * D];   // fp16 mirror of A (gather operand for spmm)
__device__ __half g_Bh[(size_t)N_NODES * D];   // fp16 mirror of B (gather operand for gx)
__device__ float  g_B[(size_t)N_NODES * D];    // fp32 accumulator; zeroed by k_combine
__device__ float  g_U[(size_t)N_NODES * D];    // ditto
__device__ float  g_acc[(size_t)N_NODES * D];  // zeroed by k_initcount each call
__device__ float  g_deg[N_NODES];              // counted in k_initcount, zeroed by k_dot
__device__ int2   g_pe[N_EDGES];               // {tu[e]|ti[e]<<16, i2c[ti[e]]}

// gx nnz sorted by DESTINATION edge (gxr): 500k bins, avg segment 4
__device__ int  g_ecnt[N_EDGES];               // counted, then zeroed by k_scanA
__device__ int  g_ecur[N_EDGES];
__device__ int  g_part[GX_BLOCKS];
__device__ int4 g_es4[NNZ_GX];                 // {srcpack, dstpack, vbits, cidx}

// g nnz sorted by DESTINATION row: 100k bins, avg segment 10
__device__ int  g_gcnt[N_NODES];
__device__ int  g_gcur[N_NODES];
__device__ int  g_gpart[G_BLOCKS];
__device__ int4 g_gs4[NNZ_G];                  // {col, row, vbits, 0}

// fire-and-forget vector reduction (RED.E.ADD.F32x4), sm_90+
__device__ __forceinline__ void red_add_f32x4(float4* addr, float4 v) {
    asm volatile("red.global.add.v4.f32 [%0], {%1, %2, %3, %4};"
                 :: "l"(addr), "f"(v.x), "f"(v.y), "f"(v.z), "f"(v.w)
                 : "memory");
}
__device__ __forceinline__ void f4add(float4& a, const float4& b) {
    a.x += b.x; a.y += b.y; a.z += b.z; a.w += b.w;
}
// gather 4 halves (8B) at idx (units of 4 halves) and widen to float4
__device__ __forceinline__ float4 ldg_h4(const __half* __restrict__ base, int idx) {
    uint2 u = ((const uint2*)base)[idx];
    __half2 h0 = *reinterpret_cast<const __half2*>(&u.x);
    __half2 h1 = *reinterpret_cast<const __half2*>(&u.y);
    float2 f0 = __half22float2(h0);
    float2 f1 = __half22float2(h1);
    return make_float4(f0.x, f0.y, f1.x, f1.y);
}
// narrow float4 to 4 halves (8B) at idx
__device__ __forceinline__ void st_h4(__half* __restrict__ base, int idx, float4 v) {
    __half2 h0 = __floats2half2_rn(v.x, v.y);
    __half2 h1 = __floats2half2_rn(v.z, v.w);
    uint2 u;
    u.x = *reinterpret_cast<unsigned*>(&h0);
    u.y = *reinterpret_cast<unsigned*>(&h1);
    ((uint2*)base)[idx] = u;
}

// 1: batched init + counts (writes fp16 A mirror)
__global__ void k_initcount(const float* __restrict__ ue, const float* __restrict__ ie,
                            const int* __restrict__ gxr, const int* __restrict__ grows,
                            const int* __restrict__ tu, const int* __restrict__ ti,
                            const int* __restrict__ i2c) {
    int t = blockIdx.x * blockDim.x + threadIdx.x;
    if (t >= PREP_T) return;
    #pragma unroll
    for (int k = 0; k < 4; ++k) {
        int i = t + k * PREP_T;
        if (i < N_NODES * DV) {
            float4 v;
            if (i < NUM_USERS * DV) v = ((const float4*)ue)[i];
            else                    v = ((const float4*)ie)[i - NUM_USERS * DV];
            st_h4(g_Ah, i, v);
            ((float4*)g_acc)[i] = make_float4(0.f, 0.f, 0.f, 0.f);
        }
    }
    int4 r4 = ((const int4*)gxr)[t];
    atomicAdd(&g_ecnt[r4.x], 1);
    atomicAdd(&g_ecnt[r4.y], 1);
    atomicAdd(&g_ecnt[r4.z], 1);
    atomicAdd(&g_ecnt[r4.w], 1);
    int2 gr2 = ((const int2*)grows)[t];
    atomicAdd(&g_gcnt[gr2.x], 1);
    atomicAdd(&g_gcnt[gr2.y], 1);
    int u = tu[t], it = ti[t];
    atomicAdd(&g_deg[u], 1.f);
    atomicAdd(&g_deg[NUM_USERS + it], 1.f);
    g_pe[t] = make_int2((int)((unsigned)u | ((unsigned)it << 16)), i2c[it]);
}

// 2: block-local scans; zero counts behind
__global__ void k_scanA() {
    __shared__ int sh[256];
    int b = blockIdx.x;
    int tid = threadIdx.x;
    int *cnt, *cur, *part;
    int n, base_bin, pidx;
    if (b < GX_BLOCKS) { cnt = g_ecnt; cur = g_ecur; part = g_part;  n = N_EDGES; base_bin = b * BINS_PER_BLOCK; pidx = b; }
    else               { cnt = g_gcnt; cur = g_gcur; part = g_gpart; n = N_NODES; base_bin = (b - GX_BLOCKS) * BINS_PER_BLOCK; pidx = b - GX_BLOCKS; }
    int i0 = base_bin + tid * 8;
    int c[8], pre[8];
    #pragma unroll
    for (int k = 0; k < 8; ++k) {
        int i = i0 + k;
        c[k] = (i < n) ? cnt[i] : 0;
    }
    pre[0] = 0;
    #pragma unroll
    for (int k = 1; k < 8; ++k) pre[k] = pre[k - 1] + c[k - 1];
    int s = pre[7] + c[7];
    sh[tid] = s;
    __syncthreads();
    for (int o = 1; o < 256; o <<= 1) {
        int v = (tid >= o) ? sh[tid - o] : 0;
        __syncthreads();
        sh[tid] += v;
        __syncthreads();
    }
    int base = (tid == 0) ? 0 : sh[tid - 1];
    #pragma unroll
    for (int k = 0; k < 8; ++k) {
        int i = i0 + k;
        if (i < n) { cur[i] = base + pre[k]; cnt[i] = 0; }
    }
    if (tid == 255) part[pidx] = sh[255];
}

// 3: scan the block-sum arrays
__global__ void k_scanB() {
    __shared__ int sh[256];
    int tid = threadIdx.x;
    int v = (tid < GX_BLOCKS) ? g_part[tid] : 0;
    sh[tid] = v;
    __syncthreads();
    for (int o = 1; o < 256; o <<= 1) {
        int u = (tid >= o) ? sh[tid - o] : 0;
        __syncthreads();
        sh[tid] += u;
        __syncthreads();
    }
    if (tid < GX_BLOCKS) g_part[tid] = sh[tid] - v;
    __syncthreads();
    int w = (tid < G_BLOCKS) ? g_gpart[tid] : 0;
    sh[tid] = w;
    __syncthreads();
    for (int o = 1; o < 256; o <<= 1) {
        int u = (tid >= o) ? sh[tid - o] : 0;
        __syncthreads();
        sh[tid] += u;
        __syncthreads();
    }
    if (tid < G_BLOCKS) g_gpart[tid] = sh[tid] - w;
}

// 4: batched scatter: 4 gx nnz + 2 g nnz per thread
__global__ void k_scatter(const int* __restrict__ gxr, const int* __restrict__ gxc,
                          const float* __restrict__ gxv,
                          const int* __restrict__ grows, const int* __restrict__ gcols,
                          const float* __restrict__ gvals) {
    int t = blockIdx.x * blockDim.x + threadIdx.x;
    if (t >= PREP_T) return;
    int4   r4 = ((const int4*)gxr)[t];
    int4   c4 = ((const int4*)gxc)[t];
    float4 v4 = ((const float4*)gxv)[t];
    int r[4] = {r4.x, r4.y, r4.z, r4.w};
    int c[4] = {c4.x, c4.y, c4.z, c4.w};
    float vv[4] = {v4.x, v4.y, v4.z, v4.w};
    int2 pc[4], pr[4];
    #pragma unroll
    for (int k = 0; k < 4; ++k) { pc[k] = g_pe[c[k]]; pr[k] = g_pe[r[k]]; }
    #pragma unroll
    for (int k = 0; k < 4; ++k) {
        int p = atomicAdd(&g_ecur[r[k]], 1) + g_part[r[k] >> 11];
        g_es4[p] = make_int4(pc[k].x, pr[k].x, __float_as_int(vv[k]), pc[k].y);
    }
    int2   row2 = ((const int2*)grows)[t];
    int2   col2 = ((const int2*)gcols)[t];
    float2 gv2  = ((const float2*)gvals)[t];
    int p0 = atomicAdd(&g_gcur[row2.x], 1) + g_gpart[row2.x >> 11];
    g_gs4[p0] = make_int4(col2.x, row2.x, __float_as_int(gv2.x), 0);
    int p1 = atomicAdd(&g_gcur[row2.y], 1) + g_gpart[row2.y >> 11];
    g_gs4[p1] = make_int4(col2.y, row2.y, __float_as_int(gv2.y), 0);
}

// 5: push spmm, 4 nnz/thread, fp16 gathers, fp32 REDs run-merged by row
__global__ void __launch_bounds__(256) k_spmm_g() {
    int t = blockIdx.x * blockDim.x + threadIdx.x;   // < NNZ_G/4 * 16 = 4M
    int p = t >> 4;
    int j = t & 15;
    if (p >= NNZ_G / 4) return;
    int4 E[4];
    #pragma unroll
    for (int k = 0; k < 4; ++k) E[k] = g_gs4[4 * p + k];
    float4 y[4];
    #pragma unroll
    for (int k = 0; k < 4; ++k) {
        float4 x = ldg_h4(g_Ah, E[k].x * DV + j);
        float v = __int_as_float(E[k].z);
        y[k] = make_float4(v * x.x, v * x.y, v * x.z, v * x.w);
    }
    float4* Bv = (float4*)g_B;
    float4 acc = y[0];
    int cur = E[0].y;
    #pragma unroll
    for (int k = 1; k < 4; ++k) {
        if (E[k].y == cur) { f4add(acc, y[k]); }
        else {
            red_add_f32x4(Bv + cur * DV + j, acc);
            cur = E[k].y;
            acc = y[k];
        }
    }
    red_add_f32x4(Bv + cur * DV + j, acc);
}

// 5b: mirror fp32 B into fp16 Bh for the gx gathers
__global__ void k_b2h() {
    int t = blockIdx.x * blockDim.x + threadIdx.x;
    if (t >= N_NODES * DV) return;
    st_h4(g_Bh, t, ((const float4*)g_B)[t]);
}

// 6: gx push, 4 nnz/thread, fp16 gathers, fp32 REDs run-merged by dst-pack
template <int LAYER0>
__global__ void __launch_bounds__(256) k_gx(const float* __restrict__ cat) {
    int t = blockIdx.x * blockDim.x + threadIdx.x;   // < NNZ_GX/4 * 16 = 8M
    int p = t >> 4;
    int j = t & 15;
    if (p >= NNZ_GX / 4) return;
    int4 E[4];
    #pragma unroll
    for (int k = 0; k < 4; ++k) E[k] = g_es4[4 * p + k];
    const float4* catv = (const float4*)cat;
    float4 yu[4], yi[4];
    #pragma unroll
    for (int k = 0; k < 4; ++k) {
        unsigned s = (unsigned)E[k].x;
        float4 x0 = ldg_h4(g_Bh, (int)(s & 0xFFFFu) * DV + j);
        float4 x1 = ldg_h4(g_Bh, (NUM_USERS + (int)(s >> 16)) * DV + j);
        if (LAYER0) {
            float4 c0 = catv[E[k].w * 32 + j];
            float4 c1 = catv[E[k].w * 32 + 16 + j];
            f4add(x0, c0);
            f4add(x1, c1);
        }
        float v = __int_as_float(E[k].z);
        yu[k] = make_float4(v * x0.x, v * x0.y, v * x0.z, v * x0.w);
        yi[k] = make_float4(v * x1.x, v * x1.y, v * x1.z, v * x1.w);
    }
    float4* Uv = (float4*)g_U;
    float4 au = yu[0], ai = yi[0];
    unsigned cur = (unsigned)E[0].y;
    #pragma unroll
    for (int k = 1; k < 4; ++k) {
        unsigned d = (unsigned)E[k].y;
        if (d == cur) { f4add(au, yu[k]); f4add(ai, yi[k]); }
        else {
            red_add_f32x4(Uv + (int)(cur & 0xFFFFu) * DV + j, au);
            red_add_f32x4(Uv + (NUM_USERS + (int)(cur >> 16)) * DV + j, ai);
            cur = d;
            au = yu[k];
            ai = yi[k];
        }
    }
    red_add_f32x4(Uv + (int)(cur & 0xFFFFu) * DV + j, au);
    red_add_f32x4(Uv + (NUM_USERS + (int)(cur >> 16)) * DV + j, ai);
}

// A = 0.5 * (U/(deg+1e-9) + B);  acc += A;  write fp16 A mirror;  zero B,U
template <int LAST>
__global__ void k_combine() {
    int t0 = (blockIdx.x * blockDim.x + threadIdx.x) * 2;
    if (t0 >= N_NODES * DV) return;
    float4 z = make_float4(0.f, 0.f, 0.f, 0.f);
    #pragma unroll
    for (int q = 0; q < 2; ++q) {
        int t = t0 + q;
        int n = t >> 4;
        float inv = 0.5f / (g_deg[n] + 1e-9f);
        float4 u = ((const float4*)g_U)[t];
        float4 b = ((const float4*)g_B)[t];
        float4 a;
        a.x = u.x * inv + 0.5f * b.x;
        a.y = u.y * inv + 0.5f * b.y;
        a.z = u.z * inv + 0.5f * b.z;
        a.w = u.w * inv + 0.5f * b.w;
        if (!LAST) st_h4(g_Ah, t, a);
        float4 ac = ((float4*)g_acc)[t];
        f4add(ac, a);
        ((float4*)g_acc)[t] = ac;
        ((float4*)g_B)[t] = z;
        ((float4*)g_U)[t] = z;
    }
}

// gamma[b] = dot(acc[u], acc[50000+i]) / 9; zero deg for next replay
__global__ void k_dot(const int* __restrict__ users, const int* __restrict__ items,
                      float* __restrict__ out) {
    int t = blockIdx.x * blockDim.x + threadIdx.x;
    if (t < N_NODES) g_deg[t] = 0.f;
    int b = t >> 5;
    if (b >= BATCH) return;
    int lane = t & 31;
    const float2* au = (const float2*)(g_acc + (size_t)users[b] * D);
    const float2* ai = (const float2*)(g_acc + (size_t)(NUM_USERS + items[b]) * D);
    float2 x = au[lane], y = ai[lane];
    float s = x.x * y.x + x.y * y.y;
    #pragma unroll
    for (int o = 16; o; o >>= 1) s += __shfl_down_sync(0xffffffffu, s, o);
    if (lane == 0) out[b] = s * (1.f / 9.f);
}

extern "C" void kernel_launch(void* const* d_in, const int* in_sizes, int n_in,
                              void* d_out, int out_size) {
    const float* user_emb = (const float*)d_in[0];
    const float* item_emb = (const float*)d_in[1];
    const float* cat_emb  = (const float*)d_in[2];
    const float* g_vals   = (const float*)d_in[3];
    const float* gx_vals  = (const float*)d_in[4];
    const int*   g_rows   = (const int*)d_in[5];
    const int*   g_cols   = (const int*)d_in[6];
    const int*   gx_rows  = (const int*)d_in[7];
    const int*   gx_cols  = (const int*)d_in[8];
    const int*   tu       = (const int*)d_in[9];
    const int*   ti       = (const int*)d_in[10];
    const int*   i2c      = (const int*)d_in[11];
    const int*   users    = (const int*)d_in[12];
    const int*   items    = (const int*)d_in[13];
    float* out = (float*)d_out;

    const int TB = 256;
    int prep_grid = (PREP_T + TB - 1) / TB;              // 1954
    int node_grid = (N_NODES * DV + TB - 1) / TB;        // 6250
    int comb_grid = (N_NODES * DV / 2 + TB - 1) / TB;    // 3125
    int g_grid    = (NNZ_G / 4 * 16) / TB;               // 15625
    int gx_grid   = (NNZ_GX / 4 * 16) / TB;              // 31250
    int dot_grid  = (BATCH * 32 + TB - 1) / TB;          // 1024

    k_initcount<<<prep_grid, TB>>>(user_emb, item_emb, gx_rows, g_rows, tu, ti, i2c); // 1
    k_scanA<<<GX_BLOCKS + G_BLOCKS, TB>>>();                                          // 2
    k_scanB<<<1, TB>>>();                                                             // 3
    k_scatter<<<prep_grid, TB>>>(gx_rows, gx_cols, gx_vals, g_rows, g_cols, g_vals);  // 4
    for (int L = 0; L < 3; ++L) {
        k_spmm_g<<<g_grid, TB>>>();                                                   // 5, 9, 13
        k_b2h<<<node_grid, TB>>>();                                                   // 6, 10, 14
        if (L == 0) k_gx<1><<<gx_grid, TB>>>(cat_emb);                                // 7, 11, 15
        else        k_gx<0><<<gx_grid, TB>>>(cat_emb);
        if (L < 2) k_combine<0><<<comb_grid, TB>>>();
        else       k_combine<1><<<comb_grid, TB>>>();
    }
    k_dot<<<dot_grid, TB>>>(users, items, out);
}

// round 17
// speedup vs baseline: 1.2645x; 1.1871x over previous
#include <cuda_runtime.h>
#include <cuda_fp16.h>

#define NUM_USERS 50000
#define NUM_ITEMS 50000
#define D 64
#define DV 16
#define N_NODES (NUM_USERS + NUM_ITEMS)
#define N_EDGES 500000
#define NNZ_G 1000000
#define NNZ_GX 2000000
#define BATCH 8192

#define BINS_PER_BLOCK 2048                 // 256 threads x 8 bins
#define GX_BLOCKS 245                       // ceil(500000/2048) gx dst-edge bins
#define G_BLOCKS  49                        // ceil(100000/2048) g row bins
#define PREP_T 500000                       // threads in batched prep kernels

// ---- static device scratch (zero-init at load; replay-safe state machine) ----
__device__ __half g_Ah[(size_t)N_NODES * D];   // fp16 mirror of A (spmm gather operand)
__device__ __half g_Bh[(size_t)N_NODES * D];   // fp16 mirror of B (gx gather operand)
__device__ float  g_B[(size_t)N_NODES * D];    // fp32 accumulator; zeroed by k_combine
__device__ float  g_U[(size_t)N_NODES * D];    // ditto
__device__ float  g_acc[(size_t)N_NODES * D];  // zeroed by k_initcount each call
__device__ float  g_deg[N_NODES];              // counted in k_initcount, zeroed by k_dot
__device__ int2   g_pe[N_EDGES];               // {tu[e]|ti[e]<<16, i2c[ti[e]]}
__device__ int    g_base[2];                   // scan block-base counters; zeroed by k_dot

// gx nnz sorted (grouped) by DESTINATION edge: 500k bins, avg segment 4
__device__ int  g_ecnt[N_EDGES];               // counted, then zeroed by k_scan
__device__ int  g_ecur[N_EDGES];
__device__ int4 g_es4[NNZ_GX];                 // {srcpack, dstpack, vbits, cidx}

// g nnz grouped by DESTINATION row: 100k bins, avg segment 10
__device__ int  g_gcnt[N_NODES];
__device__ int  g_gcur[N_NODES];
__device__ int4 g_gs4[NNZ_G];                  // {col, row, vbits, 0}

// fire-and-forget vector reduction (RED.E.ADD.F32x4), sm_90+
__device__ __forceinline__ void red_add_f32x4(float4* addr, float4 v) {
    asm volatile("red.global.add.v4.f32 [%0], {%1, %2, %3, %4};"
                 :: "l"(addr), "f"(v.x), "f"(v.y), "f"(v.z), "f"(v.w)
                 : "memory");
}
__device__ __forceinline__ void f4add(float4& a, const float4& b) {
    a.x += b.x; a.y += b.y; a.z += b.z; a.w += b.w;
}
__device__ __forceinline__ void f4fma(float4& a, float v, const float4& x) {
    a.x += v * x.x; a.y += v * x.y; a.z += v * x.z; a.w += v * x.w;
}
__device__ __forceinline__ float4 ldg_h4(const __half* __restrict__ base, int idx) {
    uint2 u = ((const uint2*)base)[idx];
    __half2 h0 = *reinterpret_cast<const __half2*>(&u.x);
    __half2 h1 = *reinterpret_cast<const __half2*>(&u.y);
    float2 f0 = __half22float2(h0);
    float2 f1 = __half22float2(h1);
    return make_float4(f0.x, f0.y, f1.x, f1.y);
}
__device__ __forceinline__ void st_h4(__half* __restrict__ base, int idx, float4 v) {
    __half2 h0 = __floats2half2_rn(v.x, v.y);
    __half2 h1 = __floats2half2_rn(v.z, v.w);
    uint2 u;
    u.x = *reinterpret_cast<unsigned*>(&h0);
    u.y = *reinterpret_cast<unsigned*>(&h1);
    ((uint2*)base)[idx] = u;
}

// 1: batched init + counts (writes fp16 A mirror)
__global__ void k_initcount(const float* __restrict__ ue, const float* __restrict__ ie,
                            const int* __restrict__ gxr, const int* __restrict__ grows,
                            const int* __restrict__ tu, const int* __restrict__ ti,
                            const int* __restrict__ i2c) {
    int t = blockIdx.x * blockDim.x + threadIdx.x;
    if (t >= PREP_T) return;
    #pragma unroll
    for (int k = 0; k < 4; ++k) {
        int i = t + k * PREP_T;
        if (i < N_NODES * DV) {
            float4 v;
            if (i < NUM_USERS * DV) v = ((const float4*)ue)[i];
            else                    v = ((const float4*)ie)[i - NUM_USERS * DV];
            st_h4(g_Ah, i, v);
            ((float4*)g_acc)[i] = make_float4(0.f, 0.f, 0.f, 0.f);
        }
    }
    int4 r4 = ((const int4*)gxr)[t];
    atomicAdd(&g_ecnt[r4.x], 1);
    atomicAdd(&g_ecnt[r4.y], 1);
    atomicAdd(&g_ecnt[r4.z], 1);
    atomicAdd(&g_ecnt[r4.w], 1);
    int2 gr2 = ((const int2*)grows)[t];
    atomicAdd(&g_gcnt[gr2.x], 1);
    atomicAdd(&g_gcnt[gr2.y], 1);
    int u = tu[t], it = ti[t];
    atomicAdd(&g_deg[u], 1.f);
    atomicAdd(&g_deg[NUM_USERS + it], 1.f);
    g_pe[t] = make_int2((int)((unsigned)u | ((unsigned)it << 16)), i2c[it]);
}

// 2: single-kernel scan: block-local prefix + atomic global block-base.
// Bin ranges are contiguous but bin ORDER is nondeterministic across calls —
// only permutes float summation order downstream (rel_err unaffected).
__global__ void k_scan() {
    __shared__ int sh[256];
    __shared__ int base_sh;
    int b = blockIdx.x;
    int tid = threadIdx.x;
    int *cnt, *cur;
    int n, base_bin, which;
    if (b < GX_BLOCKS) { cnt = g_ecnt; cur = g_ecur; n = N_EDGES; base_bin = b * BINS_PER_BLOCK; which = 0; }
    else               { cnt = g_gcnt; cur = g_gcur; n = N_NODES; base_bin = (b - GX_BLOCKS) * BINS_PER_BLOCK; which = 1; }
    int i0 = base_bin + tid * 8;
    int c[8], pre[8];
    #pragma unroll
    for (int k = 0; k < 8; ++k) {
        int i = i0 + k;
        c[k] = (i < n) ? cnt[i] : 0;
    }
    pre[0] = 0;
    #pragma unroll
    for (int k = 1; k < 8; ++k) pre[k] = pre[k - 1] + c[k - 1];
    int s = pre[7] + c[7];
    sh[tid] = s;
    __syncthreads();
    for (int o = 1; o < 256; o <<= 1) {
        int v = (tid >= o) ? sh[tid - o] : 0;
        __syncthreads();
        sh[tid] += v;
        __syncthreads();
    }
    if (tid == 255) base_sh = atomicAdd(&g_base[which], sh[255]);
    __syncthreads();
    int base = base_sh + ((tid == 0) ? 0 : sh[tid - 1]);
    #pragma unroll
    for (int k = 0; k < 8; ++k) {
        int i = i0 + k;
        if (i < n) { cur[i] = base + pre[k]; cnt[i] = 0; }
    }
}

// 3: batched scatter: 4 gx nnz + 2 g nnz per thread
__global__ void k_scatter(const int* __restrict__ gxr, const int* __restrict__ gxc,
                          const float* __restrict__ gxv,
                          const int* __restrict__ grows, const int* __restrict__ gcols,
                          const float* __restrict__ gvals) {
    int t = blockIdx.x * blockDim.x + threadIdx.x;
    if (t >= PREP_T) return;
    int4   r4 = ((const int4*)gxr)[t];
    int4   c4 = ((const int4*)gxc)[t];
    float4 v4 = ((const float4*)gxv)[t];
    int r[4] = {r4.x, r4.y, r4.z, r4.w};
    int c[4] = {c4.x, c4.y, c4.z, c4.w};
    float vv[4] = {v4.x, v4.y, v4.z, v4.w};
    int2 pc[4], pr[4];
    #pragma unroll
    for (int k = 0; k < 4; ++k) { pc[k] = g_pe[c[k]]; pr[k] = g_pe[r[k]]; }
    #pragma unroll
    for (int k = 0; k < 4; ++k) {
        int p = atomicAdd(&g_ecur[r[k]], 1);
        g_es4[p] = make_int4(pc[k].x, pr[k].x, __float_as_int(vv[k]), pc[k].y);
    }
    int2   row2 = ((const int2*)grows)[t];
    int2   col2 = ((const int2*)gcols)[t];
    float2 gv2  = ((const float2*)gvals)[t];
    int p0 = atomicAdd(&g_gcur[row2.x], 1);
    g_gs4[p0] = make_int4(col2.x, row2.x, __float_as_int(gv2.x), 0);
    int p1 = atomicAdd(&g_gcur[row2.y], 1);
    g_gs4[p1] = make_int4(col2.y, row2.y, __float_as_int(gv2.y), 0);
}

// 4: push spmm, 8 nnz/thread, fp16 gathers (two-phase), fp32 REDs run-merged
__global__ void __launch_bounds__(256) k_spmm_g() {
    int t = blockIdx.x * blockDim.x + threadIdx.x;   // < NNZ_G/8 * 16 = 2M
    int p = t >> 4;
    int j = t & 15;
    if (p >= NNZ_G / 8) return;
    int4 E[8];
    #pragma unroll
    for (int k = 0; k < 8; ++k) E[k] = g_gs4[8 * p + k];
    float4* Bv = (float4*)g_B;
    float4 acc = make_float4(0.f, 0.f, 0.f, 0.f);
    int cur = E[0].y;
    #pragma unroll
    for (int cph = 0; cph < 2; ++cph) {
        float4 x[4];
        #pragma unroll
        for (int k = 0; k < 4; ++k) x[k] = ldg_h4(g_Ah, E[4 * cph + k].x * DV + j);
        #pragma unroll
        for (int k = 0; k < 4; ++k) {
            int kk = 4 * cph + k;
            if (E[kk].y != cur) {
                red_add_f32x4(Bv + cur * DV + j, acc);
                cur = E[kk].y;
                acc = make_float4(0.f, 0.f, 0.f, 0.f);
            }
            f4fma(acc, __int_as_float(E[kk].z), x[k]);
        }
    }
    red_add_f32x4(Bv + cur * DV + j, acc);
}

// 4b: mirror fp32 B into fp16 Bh for the gx gathers
__global__ void k_b2h() {
    int t = blockIdx.x * blockDim.x + threadIdx.x;
    if (t >= N_NODES * DV) return;
    st_h4(g_Bh, t, ((const float4*)g_B)[t]);
}

// 5: gx push, 8 nnz/thread, fp16 gathers (two-phase), run-merge RED pairs
template <int LAYER0>
__global__ void __launch_bounds__(256) k_gx(const float* __restrict__ cat) {
    int t = blockIdx.x * blockDim.x + threadIdx.x;   // < NNZ_GX/8 * 16 = 4M
    int p = t >> 4;
    int j = t & 15;
    if (p >= NNZ_GX / 8) return;
    int4 E[8];
    #pragma unroll
    for (int k = 0; k < 8; ++k) E[k] = g_es4[8 * p + k];
    const float4* catv = (const float4*)cat;
    float4* Uv = (float4*)g_U;
    float4 au = make_float4(0.f, 0.f, 0.f, 0.f);
    float4 ai = make_float4(0.f, 0.f, 0.f, 0.f);
    unsigned cur = (unsigned)E[0].y;
    #pragma unroll
    for (int cph = 0; cph < 2; ++cph) {
        float4 x0[4], x1[4];
        #pragma unroll
        for (int k = 0; k < 4; ++k) {
            int kk = 4 * cph + k;
            unsigned s = (unsigned)E[kk].x;
            x0[k] = ldg_h4(g_Bh, (int)(s & 0xFFFFu) * DV + j);
            x1[k] = ldg_h4(g_Bh, (NUM_USERS + (int)(s >> 16)) * DV + j);
            if (LAYER0) {
                f4add(x0[k], catv[E[kk].w * 32 + j]);
                f4add(x1[k], catv[E[kk].w * 32 + 16 + j]);
            }
        }
        #pragma unroll
        for (int k = 0; k < 4; ++k) {
            int kk = 4 * cph + k;
            unsigned d = (unsigned)E[kk].y;
            if (d != cur) {
                red_add_f32x4(Uv + (int)(cur & 0xFFFFu) * DV + j, au);
                red_add_f32x4(Uv + (NUM_USERS + (int)(cur >> 16)) * DV + j, ai);
                cur = d;
                au = make_float4(0.f, 0.f, 0.f, 0.f);
                ai = make_float4(0.f, 0.f, 0.f, 0.f);
            }
            float v = __int_as_float(E[kk].z);
            f4fma(au, v, x0[k]);
            f4fma(ai, v, x1[k]);
        }
    }
    red_add_f32x4(Uv + (int)(cur & 0xFFFFu) * DV + j, au);
    red_add_f32x4(Uv + (NUM_USERS + (int)(cur >> 16)) * DV + j, ai);
}

// A = 0.5 * (U/(deg+1e-9) + B);  acc += A;  fp16 A mirror;  zero B,U
template <int LAST>
__global__ void k_combine() {
    int t0 = (blockIdx.x * blockDim.x + threadIdx.x) * 2;
    if (t0 >= N_NODES * DV) return;
    float4 z = make_float4(0.f, 0.f, 0.f, 0.f);
    #pragma unroll
    for (int q = 0; q < 2; ++q) {
        int t = t0 + q;
        int n = t >> 4;
        float inv = 0.5f / (g_deg[n] + 1e-9f);
        float4 u = ((const float4*)g_U)[t];
        float4 b = ((const float4*)g_B)[t];
        float4 a;
        a.x = u.x * inv + 0.5f * b.x;
        a.y = u.y * inv + 0.5f * b.y;
        a.z = u.z * inv + 0.5f * b.z;
        a.w = u.w * inv + 0.5f * b.w;
        if (!LAST) st_h4(g_Ah, t, a);
        float4 ac = ((float4*)g_acc)[t];
        f4add(ac, a);
        ((float4*)g_acc)[t] = ac;
        ((float4*)g_B)[t] = z;
        ((float4*)g_U)[t] = z;
    }
}

// gamma[b] = dot(acc[u], acc[50000+i]) / 9; zero deg + scan bases for replay
__global__ void k_dot(const int* __restrict__ users, const int* __restrict__ items,
                      float* __restrict__ out) {
    int t = blockIdx.x * blockDim.x + threadIdx.x;
    if (t < N_NODES) g_deg[t] = 0.f;
    if (t < 2) g_base[t] = 0;
    int b = t >> 5;
    if (b >= BATCH) return;
    int lane = t & 31;
    const float2* au = (const float2*)(g_acc + (size_t)users[b] * D);
    const float2* ai = (const float2*)(g_acc + (size_t)(NUM_USERS + items[b]) * D);
    float2 x = au[lane], y = ai[lane];
    float s = x.x * y.x + x.y * y.y;
    #pragma unroll
    for (int o = 16; o; o >>= 1) s += __shfl_down_sync(0xffffffffu, s, o);
    if (lane == 0) out[b] = s * (1.f / 9.f);
}

extern "C" void kernel_launch(void* const* d_in, const int* in_sizes, int n_in,
                              void* d_out, int out_size) {
    const float* user_emb = (const float*)d_in[0];
    const float* item_emb = (const float*)d_in[1];
    const float* cat_emb  = (const float*)d_in[2];
    const float* g_vals   = (const float*)d_in[3];
    const float* gx_vals  = (const float*)d_in[4];
    const int*   g_rows   = (const int*)d_in[5];
    const int*   g_cols   = (const int*)d_in[6];
    const int*   gx_rows  = (const int*)d_in[7];
    const int*   gx_cols  = (const int*)d_in[8];
    const int*   tu       = (const int*)d_in[9];
    const int*   ti       = (const int*)d_in[10];
    const int*   i2c      = (const int*)d_in[11];
    const int*   users    = (const int*)d_in[12];
    const int*   items    = (const int*)d_in[13];
    float* out = (float*)d_out;

    const int TB = 256;
    int prep_grid = (PREP_T + TB - 1) / TB;              // 1954
    int node_grid = (N_NODES * DV + TB - 1) / TB;        // 6250
    int comb_grid = (N_NODES * DV / 2 + TB - 1) / TB;    // 3125
    int g_grid    = (NNZ_G / 8 * 16 + TB - 1) / TB;      // 7813
    int gx_grid   = (NNZ_GX / 8 * 16) / TB;              // 15625
    int dot_grid  = (BATCH * 32 + TB - 1) / TB;          // 1024

    k_initcount<<<prep_grid, TB>>>(user_emb, item_emb, gx_rows, g_rows, tu, ti, i2c); // 1
    k_scan<<<GX_BLOCKS + G_BLOCKS, TB>>>();                                           // 2
    k_scatter<<<prep_grid, TB>>>(gx_rows, gx_cols, gx_vals, g_rows, g_cols, g_vals);  // 3
    for (int L = 0; L < 3; ++L) {
        k_spmm_g<<<g_grid, TB>>>();                                                   // 4 <- profiled
        k_b2h<<<node_grid, TB>>>();
        if (L == 0) k_gx<1><<<gx_grid, TB>>>(cat_emb);
        else        k_gx<0><<<gx_grid, TB>>>(cat_emb);
        if (L < 2) k_combine<0><<<comb_grid, TB>>>();
        else       k_combine<1><<<comb_grid, TB>>>();
    }
    k_dot<<<dot_grid, TB>>>(users, items, out);
}